// round 17
// baseline (speedup 1.0000x reference)
#include <cuda_runtime.h>
#include <math.h>

// ---------------------------------------------------------------------------
// OwlViT prediction head
//   B=32, P=576, DV=768, DT=512, N_PARTS=12, K=3, NUM_CLASSES=800
//   out = [logits_reshaped (384*9600) | pred_logits (32*800)] fp32
// ---------------------------------------------------------------------------

#define Bsz 32
#define Pn 576
#define DV 768
#define DT 512
#define NPART 12
#define TOPK 3
#define NCLS 800
#define NQ (NCLS * NPART)      // 9600 query rows per batch
#define MROWS (Bsz * NPART)    // 384
#define LOGITS_ELEMS ((size_t)MROWS * NQ)

// scratch (static device memory; no allocations allowed)
__device__ float g_h1[MROWS * DV];
__device__ float g_h2[MROWS * DV];
__device__ float g_img[MROWS * DT];

// ---------------------------------------------------------------------------
__device__ __forceinline__ void fma2(unsigned long long& d,
                                     unsigned long long a,
                                     unsigned long long b) {
    asm("fma.rn.f32x2 %0, %1, %2, %0;" : "+l"(d) : "l"(a), "l"(b));
}

__device__ __forceinline__ float pair_sum(unsigned long long v) {
    float lo = __uint_as_float((unsigned)(v & 0xffffffffull));
    float hi = __uint_as_float((unsigned)(v >> 32));
    return lo + hi;
}

__device__ __forceinline__ float gelu_exact(float x) {
    return 0.5f * x * (1.0f + erff(x * 0.70710678118654752f));
}

__device__ __forceinline__ void cp_async16(unsigned dst, const void* src) {
    asm volatile("cp.async.cg.shared.global [%0], [%1], 16;"
                 :: "r"(dst), "l"(src));
}
__device__ __forceinline__ void cp_commit() {
    asm volatile("cp.async.commit_group;");
}
__device__ __forceinline__ void cp_wait2() {
    asm volatile("cp.async.wait_group 2;");
}
__device__ __forceinline__ void cp_wait1() {
    asm volatile("cp.async.wait_group 1;");
}
__device__ __forceinline__ void cp_wait0() {
    asm volatile("cp.async.wait_group 0;");
}

// ---------------------------------------------------------------------------
// GEMM: C[M,N] = gelu(A[M,768] * W[N,768]^T + bias), smem double-buffered.
// BM=32 BN=64 BK=32, 256 threads, 2x4 outputs/thread, f32x2 k-pair FMAs.
// GATHER=true: A row r is the dedup-sum of topk image rows (fused gather).
// ---------------------------------------------------------------------------
#define GBM 32
#define GBN 64
#define GBK 32
#define GPAD 36
#define NITER (DV / GBK)   // 24

template<bool GATHER>
__global__ void __launch_bounds__(256)
gemm_kernel(const float* __restrict__ A, const float* __restrict__ W,
            const float* __restrict__ bias, float* __restrict__ C, int N,
            const int* __restrict__ idx) {
    __shared__ __align__(16) float As[2][GBM][GPAD];
    __shared__ __align__(16) float Ws[2][GBN][GPAD];
    int t = threadIdx.x;
    int tx = t & 15;                 // cols tx + 16j
    int ty = t >> 4;                 // rows ty*2 + i
    int bm = blockIdx.x * GBM, bn = blockIdx.y * GBN;

    int ar = t >> 3, ak = (t & 7) * 4;    // A tile: 1 float4/thread
    int wr = t >> 2, wk = (t & 3) * 8;    // W tile: 2 float4/thread

    const float *Arow0, *Arow1, *Arow2;
    bool u1 = false, u2 = false;
    if (GATHER) {
        int row = bm + ar;
        int bb = row / NPART, n = row - bb * NPART;
        int i0 = idx[(bb * TOPK + 0) * NPART + n];
        int i1 = idx[(bb * TOPK + 1) * NPART + n];
        int i2 = idx[(bb * TOPK + 2) * NPART + n];
        i0 = min(max(i0, 0), Pn - 1);
        i1 = min(max(i1, 0), Pn - 1);
        i2 = min(max(i2, 0), Pn - 1);
        u1 = (i1 != i0);
        u2 = (i2 != i0) && (i2 != i1);
        const float* base = A + (size_t)bb * Pn * DV;
        Arow0 = base + (size_t)i0 * DV;
        Arow1 = base + (size_t)i1 * DV;
        Arow2 = base + (size_t)i2 * DV;
    } else {
        Arow0 = A + (size_t)(bm + ar) * DV;
        Arow1 = Arow0; Arow2 = Arow0;
    }
    const float* Wg = W + (size_t)(bn + wr) * DV;

    auto loadA = [&](int k0) -> float4 {
        float4 s = *(const float4*)(Arow0 + k0 + ak);
        if (GATHER) {
            if (u1) { float4 v = *(const float4*)(Arow1 + k0 + ak);
                      s.x += v.x; s.y += v.y; s.z += v.z; s.w += v.w; }
            if (u2) { float4 v = *(const float4*)(Arow2 + k0 + ak);
                      s.x += v.x; s.y += v.y; s.z += v.z; s.w += v.w; }
        }
        return s;
    };

    unsigned long long acc2[2][4];
#pragma unroll
    for (int i = 0; i < 2; ++i)
#pragma unroll
        for (int j = 0; j < 4; ++j) acc2[i][j] = 0ull;

    // prologue: tile0 -> smem[0]; tile1 -> regs
    float4 a_r = loadA(0);
    float4 w_r0 = *(const float4*)(Wg + wk);
    float4 w_r1 = *(const float4*)(Wg + wk + 4);
    *(float4*)&As[0][ar][ak] = a_r;
    *(float4*)&Ws[0][wr][wk] = w_r0;
    *(float4*)&Ws[0][wr][wk + 4] = w_r1;
    a_r  = loadA(GBK);
    w_r0 = *(const float4*)(Wg + GBK + wk);
    w_r1 = *(const float4*)(Wg + GBK + wk + 4);
    __syncthreads();

#pragma unroll 1
    for (int i = 0; i < NITER; ++i) {
        int buf = i & 1, nbuf = buf ^ 1;
        if (i + 1 < NITER) {
            *(float4*)&As[nbuf][ar][ak] = a_r;
            *(float4*)&Ws[nbuf][wr][wk] = w_r0;
            *(float4*)&Ws[nbuf][wr][wk + 4] = w_r1;
        }
        if (i + 2 < NITER) {
            int k0 = (i + 2) * GBK;
            a_r  = loadA(k0);
            w_r0 = *(const float4*)(Wg + k0 + wk);
            w_r1 = *(const float4*)(Wg + k0 + wk + 4);
        }
#pragma unroll
        for (int kk = 0; kk < GBK; kk += 4) {
            ulonglong2 ap[2], wp[4];
            ap[0] = *(const ulonglong2*)&As[buf][ty * 2][kk];
            ap[1] = *(const ulonglong2*)&As[buf][ty * 2 + 1][kk];
#pragma unroll
            for (int j = 0; j < 4; ++j)
                wp[j] = *(const ulonglong2*)&Ws[buf][tx + 16 * j][kk];
#pragma unroll
            for (int ii = 0; ii < 2; ++ii)
#pragma unroll
                for (int j = 0; j < 4; ++j) {
                    fma2(acc2[ii][j], ap[ii].x, wp[j].x);
                    fma2(acc2[ii][j], ap[ii].y, wp[j].y);
                }
        }
        __syncthreads();
    }

#pragma unroll
    for (int i = 0; i < 2; ++i) {
        int row = bm + ty * 2 + i;
#pragma unroll
        for (int j = 0; j < 4; ++j) {
            int col = bn + tx + 16 * j;
            float x = pair_sum(acc2[i][j]) + bias[col];
            C[(size_t)row * N + col] = gelu_exact(x);
        }
    }
}

// ---------------------------------------------------------------------------
// logits: PER-WARP cp.async pipelines, 6 warps/block, unrolled x4 main loop.
// Warp w owns rows {r0 + w*64 + l, +32} (RPT=2). Each warp stages its own
// 64-row x 8-k tiles (2KB) into a private 4-buffer ring.
// Per tile: wait_group -> __syncwarp -> issue tile+3 -> compute; buffer
// index and issue target are COMPILE-TIME within the x4-unrolled body.
//
// Pending-group ledger (R16 bug fix): main loop runs tiles 0..59, issuing
// tiles 3..62. Tail tile 60 MUST issue tile 63 (R16 skipped it -> buf 3
// held stale tile-59 data and tail waits under-counted -> rel_err 0.24).
//   tile 60: pending {60,61,62} -> wait2; issue 63 -> {61,62,63}
//   tile 61: wait2 drains 61; tile 62: wait1; tile 63: wait0.
// TPB=192, 3 blocks/SM (72KB smem: 48KB q + 24KB img), regs capped at 112
// -> 18 warps/SM.
// ---------------------------------------------------------------------------
#define QT 8
#define NT (DT / QT)     // 64 tiles
#define RPT 2
#define TPB 192
#define NWARP 6
#define RPB (NWARP * 64) // 384; grid.x = 9600/384 = 25 (exact, no guards)
#define WROWS 64         // rows per warp
#define WBUF 128         // float4 per warp buffer (2 slots x 64 rows) = 2KB

__global__ void __launch_bounds__(TPB, 3)
logits_kernel(const float* __restrict__ q, float* __restrict__ out) {
    extern __shared__ __align__(16) float smem[];
    float4* q_s  = (float4*)smem;          // [6 warps][4 bufs][128] = 48KB
    float* img_s = smem + 12288;           // 12*512 floats = 24KB

    int t = threadIdx.x;
    int warp = t / 32, lane = t & 31;
    int b = blockIdx.y;
    int r0 = blockIdx.x * RPB;

    const float* qB = q + (size_t)b * NQ * DT;

    // --- per-warp staging setup: 4 float4/lane/tile ---
    // idx = j*32 + lane -> row = idx>>1 (2 lanes per row), slot = idx&1.
    float4* wq = q_s + warp * (4 * WBUF);  // this warp's 4-buffer ring
    const float* srcp[4];
    unsigned dst0[4];                      // dst smem addr within buf 0
#pragma unroll
    for (int j = 0; j < 4; ++j) {
        int idx = j * 32 + lane;
        int row = idx >> 1, slot = idx & 1;
        int rg = r0 + warp * WROWS + row;  // grid divides exactly: in range
        srcp[j] = qB + (size_t)rg * DT + slot * 4;
        int rr = (row + 4 * slot) & (WROWS - 1);           // rotation: slot1 +4
        dst0[j] = (unsigned)__cvta_generic_to_shared(
            &wq[slot * WROWS + rr]);
    }

    auto issueTile = [&](int buf) {
        unsigned boff = (unsigned)buf * (WBUF * 16);       // bytes per buffer
#pragma unroll
        for (int j = 0; j < 4; ++j) {
            cp_async16(dst0[j] + boff, srcp[j]);
            srcp[j] += QT;
        }
        cp_commit();
    };

    // prologue: 3 groups in flight before first compute
    issueTile(0);
    issueTile(1);
    issueTile(2);

    {   // stage img tile for this batch (1536 float4, 8/thread)
        const float4* src = (const float4*)(g_img + (size_t)b * NPART * DT);
        float4* dst = (float4*)img_s;
#pragma unroll
        for (int i = 0; i < 8; ++i)
            dst[t + i * TPB] = src[t + i * TPB];
    }
    __syncthreads();

    // fused l2 normalization of the 12 img rows (6 warps, 2 rows each)
    for (int row = warp; row < NPART; row += NWARP) {
        float* rp = img_s + row * DT;
        float4 v0 = *(float4*)(rp + lane * 4);
        float4 v1 = *(float4*)(rp + lane * 4 + 128);
        float4 v2 = *(float4*)(rp + lane * 4 + 256);
        float4 v3 = *(float4*)(rp + lane * 4 + 384);
        float ss = v0.x*v0.x + v0.y*v0.y + v0.z*v0.z + v0.w*v0.w
                 + v1.x*v1.x + v1.y*v1.y + v1.z*v1.z + v1.w*v1.w
                 + v2.x*v2.x + v2.y*v2.y + v2.z*v2.z + v2.w*v2.w
                 + v3.x*v3.x + v3.y*v3.y + v3.z*v3.z + v3.w*v3.w;
#pragma unroll
        for (int off = 16; off > 0; off >>= 1)
            ss += __shfl_xor_sync(0xffffffffu, ss, off);
        float rinv = 1.0f / fmaxf(sqrtf(ss), 1e-12f);
        v0.x*=rinv; v0.y*=rinv; v0.z*=rinv; v0.w*=rinv;
        v1.x*=rinv; v1.y*=rinv; v1.z*=rinv; v1.w*=rinv;
        v2.x*=rinv; v2.y*=rinv; v2.z*=rinv; v2.w*=rinv;
        v3.x*=rinv; v3.y*=rinv; v3.z*=rinv; v3.w*=rinv;
        *(float4*)(rp + lane * 4)       = v0;
        *(float4*)(rp + lane * 4 + 128) = v1;
        *(float4*)(rp + lane * 4 + 256) = v2;
        *(float4*)(rp + lane * 4 + 384) = v3;
    }
    __syncthreads();   // img_s final for all warps; last block-wide barrier

    // hoisted, tile-invariant q LDS indices: [r][c] -> c*WROWS + rotated row
    int qidx[RPT][2];
#pragma unroll
    for (int r = 0; r < RPT; ++r)
#pragma unroll
        for (int c = 0; c < 2; ++c)
            qidx[r][c] = c * WROWS + ((lane + 32 * r + 4 * c) & (WROWS - 1));

    unsigned long long acc[RPT][13];
#pragma unroll
    for (int r = 0; r < RPT; ++r)
#pragma unroll
        for (int j = 0; j < 13; ++j) acc[r][j] = 0ull;

    // one tile step: buf/koff compile-time inside unrolled bodies.
    // WAIT: 0->wait2, 1->wait1, 2->wait0. ISSUE: stage next into (buf+3)&3.
    auto step = [&](int buf, int koff, int wait, bool issue) {
        if (wait == 0) cp_wait2();
        else if (wait == 1) cp_wait1();
        else cp_wait0();
        __syncwarp();
        if (issue) issueTile((buf + 3) & 3);
        const float4* qbuf = wq + buf * WBUF;
        const float* ik = img_s + koff;
#pragma unroll
        for (int c = 0; c < 2; ++c) {
            ulonglong2 qp[RPT];
#pragma unroll
            for (int r = 0; r < RPT; ++r)
                qp[r] = *(const ulonglong2*)&qbuf[qidx[r][c]];
#pragma unroll
            for (int n = 0; n < NPART; ++n) {
                ulonglong2 im = *(const ulonglong2*)&ik[n * DT + c * 4];
#pragma unroll
                for (int r = 0; r < RPT; ++r) {
                    fma2(acc[r][n], qp[r].x, im.x);
                    fma2(acc[r][n], qp[r].y, im.y);
                }
            }
#pragma unroll
            for (int r = 0; r < RPT; ++r) {
                fma2(acc[r][12], qp[r].x, qp[r].x);
                fma2(acc[r][12], qp[r].y, qp[r].y);
            }
        }
    };

    // main: tiles 0..NT-5 in groups of 4 (NT-4 = 60, divisible by 4),
    // issuing tiles 3..62.
#pragma unroll 1
    for (int base = 0; base < NT - 4; base += 4) {
        int koff = base * QT;
#pragma unroll
        for (int u = 0; u < 4; ++u)
            step(u, koff + u * QT, 0, true);
    }
    // peeled tail: tiles 60..63 (bufs 0..3).
    // Tile 60 ISSUES tile 63 (the R16 bug: omitted -> stale buf 3).
    {
        int koff = (NT - 4) * QT;
        step(0, koff, 0, true);           // tile 60: wait2; issue 63
        step(1, koff + QT, 0, false);     // tile 61: {61,62,63} -> wait2
        step(2, koff + 2 * QT, 1, false); // tile 62: {62,63}    -> wait1
        step(3, koff + 3 * QT, 2, false); // tile 63: {63}       -> wait0
    }

#pragma unroll
    for (int r = 0; r < RPT; ++r) {
        int gr = r0 + warp * WROWS + lane + 32 * r;
        float s[13];
#pragma unroll
        for (int j = 0; j < 13; ++j) s[j] = pair_sum(acc[r][j]);
        float rinv = 1.0f / fmaxf(sqrtf(s[12]), 1e-12f);
#pragma unroll
        for (int n = 0; n < NPART; ++n)
            out[((size_t)(b * NPART + n)) * NQ + gr] = s[n] * rinv;
    }
}

// ---------------------------------------------------------------------------
// pred_logits[b,c] = sum_n logits[b,n,c*12+n]
// ---------------------------------------------------------------------------
__global__ void pred_kernel(float* __restrict__ out) {
    int t = blockIdx.x * blockDim.x + threadIdx.x;   // 0..25599
    if (t >= Bsz * NCLS) return;
    int b = t / NCLS, c = t % NCLS;
    float s = 0.0f;
#pragma unroll
    for (int n = 0; n < NPART; ++n)
        s += out[((size_t)(b * NPART + n)) * NQ + c * NPART + n];
    out[LOGITS_ELEMS + t] = s;
}

// ---------------------------------------------------------------------------
extern "C" void kernel_launch(void* const* d_in, const int* in_sizes, int n_in,
                              void* d_out, int out_size) {
    const float* image = (const float*)d_in[0];
    const float* query = (const float*)d_in[1];
    const int* topk = (const int*)d_in[2];
    const float* W1 = (const float*)d_in[3];
    const float* b1 = (const float*)d_in[4];
    const float* W2 = (const float*)d_in[5];
    const float* b2 = (const float*)d_in[6];
    const float* W3 = (const float*)d_in[7];
    const float* b3 = (const float*)d_in[8];
    float* out = (float*)d_out;

    float* h1; float* h2; float* img;
    cudaGetSymbolAddress((void**)&h1, g_h1);
    cudaGetSymbolAddress((void**)&h2, g_h2);
    cudaGetSymbolAddress((void**)&img, g_img);

    const int LOGITS_SMEM = 73728;   // 48KB q (6 warps x 4 bufs) + 24KB img
    cudaFuncSetAttribute(logits_kernel,
                         cudaFuncAttributeMaxDynamicSharedMemorySize,
                         LOGITS_SMEM);

    // launch order keeps logits at global index 5 (2 harness preamble
    // launches + 3 here) so ncu -s 5 -c 1 captures it.
    gemm_kernel<true ><<<dim3(MROWS / GBM, DV / GBN), 256>>>(image, W1, b1, h1, DV, topk);
    gemm_kernel<false><<<dim3(MROWS / GBM, DV / GBN), 256>>>(h1, W2, b2, h2, DV, nullptr);
    gemm_kernel<false><<<dim3(MROWS / GBM, DT / GBN), 256>>>(h2, W3, b3, img, DT, nullptr);
    logits_kernel<<<dim3(NQ / RPB, Bsz), TPB, LOGITS_SMEM>>>(query, out);
    pred_kernel<<<(Bsz * NCLS + 255) / 256, 256>>>(out);
}